// round 9
// baseline (speedup 1.0000x reference)
#include <cuda_runtime.h>
#include <cuda_bf16.h>

// Welford over batch dim of x: (B, C, H, W) = (256, 64, 64, 64).
// R9 design: batch-split (4 chunks x 64 samples) x float4 positions.
//   - 262,144 threads (same warp pool as R1) but each issues only 64 LDG.128 +
//     64 STG.128 instead of 256+256 32-bit ops -> LSU issue and the MLP=1
//     latency chain both drop ~4x below the DRAM time; kernel becomes HBM-bound.
//   - Chunk 0 continues the input (m,s,nn,n) state; chunks 1-3 run standalone
//     Welford from zero. Partials land in __device__ scratch; a small second
//     kernel merges 4-way with Chan's exact formula.
//
// Output layout (float32, concatenated):
//   [0, B*CHW) : x passthrough | [+0,+CHW): m | [+CHW,+2CHW): s
//   [+2CHW,+3CHW): neuron_nonzero | [last]: n_samples + B

#define MAX_CHW4 65536           // CHW/4 for the fixed 64*64*64 shape
#define NGROUP   4

static __device__ float4 g_mpart[NGROUP * MAX_CHW4];
static __device__ float4 g_spart[NGROUP * MAX_CHW4];
static __device__ int4   g_nnpart[NGROUP * MAX_CHW4];

// lane-wise Welford step on one float4 sample
#define WELF4(xv)                                                              \
    do {                                                                       \
        float inv = __fdividef(1.0f, nf + 1.0f);                               \
        nn.x += ((xv).x != 0.0f);                                              \
        nn.y += ((xv).y != 0.0f);                                              \
        nn.z += ((xv).z != 0.0f);                                              \
        nn.w += ((xv).w != 0.0f);                                              \
        float om;                                                              \
        om = m.x; m.x += ((xv).x - m.x) * inv; s.x += ((xv).x - m.x) * ((xv).x - om); \
        om = m.y; m.y += ((xv).y - m.y) * inv; s.y += ((xv).y - m.y) * ((xv).y - om); \
        om = m.z; m.z += ((xv).z - m.z) * inv; s.z += ((xv).z - m.z) * ((xv).z - om); \
        om = m.w; m.w += ((xv).w - m.w) * inv; s.w += ((xv).w - m.w) * ((xv).w - om); \
        nf += 1.0f;                                                            \
    } while (0)

__global__ void __launch_bounds__(256) welford_part(
    const float4* __restrict__ x,
    const float4* __restrict__ m_in,
    const float4* __restrict__ s_in,
    const int4*   __restrict__ nn_in,
    const int*    __restrict__ n_in,
    float4*       __restrict__ out4,
    int CHW4, int BCHUNK)       // CHW4 = CHW/4, BCHUNK = B/NGROUP
{
    // blocks [0,256) -> group 0, [256,512) -> group 1, ...
    const int blocksPerGroup = CHW4 / 256;          // 256 for the fixed shape
    int g   = blockIdx.x / blocksPerGroup;
    int p4  = (blockIdx.x % blocksPerGroup) * 256 + threadIdx.x;
    if (p4 >= CHW4) return;

    float4 m, s;
    int4 nn;
    float nf;
    if (g == 0) {
        m  = m_in[p4];
        s  = s_in[p4];
        nn = nn_in[p4];
        nf = (float)n_in[0];
    } else {
        m = make_float4(0.f, 0.f, 0.f, 0.f);
        s = make_float4(0.f, 0.f, 0.f, 0.f);
        nn = make_int4(0, 0, 0, 0);
        nf = 0.0f;
    }

    const float4* xp = x    + (size_t)g * BCHUNK * CHW4 + p4;
    float4*       op = out4 + (size_t)g * BCHUNK * CHW4 + p4;

    #pragma unroll 4
    for (int b = 0; b < BCHUNK; ++b) {
        float4 xv = xp[(size_t)b * CHW4];
        op[(size_t)b * CHW4] = xv;              // passthrough of x
        WELF4(xv);
    }

    g_mpart [g * CHW4 + p4] = m;
    g_spart [g * CHW4 + p4] = s;
    g_nnpart[g * CHW4 + p4] = nn;
}

__global__ void __launch_bounds__(256) welford_merge(
    const int* __restrict__ n_in,
    float*     __restrict__ out,
    int CHW4, int B, int BCHUNK)
{
    int p4 = blockIdx.x * blockDim.x + threadIdx.x;
    if (p4 >= CHW4) return;

    const float n0 = (float)n_in[0];

    float4 m  = g_mpart[p4];
    float4 s  = g_spart[p4];
    int4   nn = g_nnpart[p4];
    float  nA = n0 + (float)BCHUNK;

    #pragma unroll
    for (int g = 1; g < NGROUP; ++g) {
        float4 mB  = g_mpart [g * CHW4 + p4];
        float4 sB  = g_spart [g * CHW4 + p4];
        int4   nnB = g_nnpart[g * CHW4 + p4];

        float nB   = (float)BCHUNK;
        float nT   = nA + nB;
        float invT = __fdividef(1.0f, nT);
        float wB   = nB * invT;          // nB / nT
        float wAB  = nA * nB * invT;     // nA*nB / nT

        float d;
        d = mB.x - m.x; m.x += d * wB; s.x = s.x + sB.x + d * d * wAB;
        d = mB.y - m.y; m.y += d * wB; s.y = s.y + sB.y + d * d * wAB;
        d = mB.z - m.z; m.z += d * wB; s.z = s.z + sB.z + d * d * wAB;
        d = mB.w - m.w; m.w += d * wB; s.w = s.w + sB.w + d * d * wAB;

        nn.x += nnB.x; nn.y += nnB.y; nn.z += nnB.z; nn.w += nnB.w;
        nA = nT;
    }

    float4* out4  = reinterpret_cast<float4*>(out);
    const size_t base4 = (size_t)B * (size_t)CHW4;    // in float4 units

    out4[base4 + p4]                    = m;
    out4[base4 + (size_t)CHW4 + p4]     = s;
    out4[base4 + 2 * (size_t)CHW4 + p4] =
        make_float4((float)nn.x, (float)nn.y, (float)nn.z, (float)nn.w);
    if (p4 == 0) {
        const size_t CHW = (size_t)CHW4 * 4;
        out[(size_t)B * CHW + 3 * CHW] = n0 + (float)B;
    }
}

extern "C" void kernel_launch(void* const* d_in, const int* in_sizes, int n_in,
                              void* d_out, int out_size)
{
    const float4* x  = (const float4*)d_in[0];
    const float4* m  = (const float4*)d_in[1];
    const float4* s  = (const float4*)d_in[2];
    const int4*   nn = (const int4*)d_in[3];
    const int*    n  = (const int*)d_in[4];
    float* out = (float*)d_out;

    const int CHW  = in_sizes[1];            // 262144
    const int B    = in_sizes[0] / CHW;      // 256
    const int CHW4 = CHW / 4;                // 65536
    const int BCHUNK = B / NGROUP;           // 64

    const int threads = 256;
    const int blocksPerGroup = CHW4 / threads;            // 256
    welford_part<<<blocksPerGroup * NGROUP, threads>>>(
        x, m, s, nn, n, (float4*)out, CHW4, BCHUNK);
    welford_merge<<<blocksPerGroup, threads>>>(n, out, CHW4, B, BCHUNK);
}

// round 10
// speedup vs baseline: 1.0650x; 1.0650x over previous
#include <cuda_runtime.h>
#include <cuda_bf16.h>

// Welford running mean/variance over batch dim of x: (B, C, H, W), B=256, CHW=262144.
// One scalar thread per spatial position (262,144 threads, R1/R4-proven warp pool).
//
// R10 = R4 (two independent half-batch Welford streams, exact Chan merge) +
//       R8 (prefetch-1 software pipeline inside each stream) => steady-state
//       MLP~4 per warp at near-full occupancy. launch_bounds(256,6) caps regs
//       at 42 so the prefetch registers survive; if ptxas still squeezes to 32
//       this degrades gracefully to exactly R4 (best bench so far).
//
// Output layout (float32, concatenated):
//   [0, B*CHW) : x passthrough | [+0,+CHW): m | [+CHW,+2CHW): s
//   [+2CHW,+3CHW): neuron_nonzero | [last]: n_samples + B

__global__ void __launch_bounds__(256, 6) welford_dual_pipe(
    const float* __restrict__ x,
    const float* __restrict__ m_in,
    const float* __restrict__ s_in,
    const int*   __restrict__ nn_in,
    const int*   __restrict__ n_in,
    float*       __restrict__ out,
    int B, int CHW)
{
    int p = blockIdx.x * blockDim.x + threadIdx.x;
    if (p >= CHW) return;

    const int H  = B >> 1;                 // 128
    const int n0 = n_in[0];
    const size_t step = (size_t)CHW;

    // Stream A continues the input state over b in [0, H);
    // Stream B runs standalone from zero over b in [H, B).
    float mA = m_in[p], sA = s_in[p];
    float mB = 0.0f,    sB = 0.0f;
    int   nnA = nn_in[p], nnB = 0;

    const float* xA = x + p;
    const float* xB = x + p + (size_t)H * step;
    float*       oA = out + p;
    float*       oB = out + p + (size_t)H * step;

    // Prologue: prefetch first sample of each stream.
    float vA = xA[0];
    float vB = xB[0];

    float nfA = (float)n0;
    float nfB = 0.0f;

    for (int b = 0; b < H - 1; ++b) {
        // Phase 1: issue next loads (independent of all pending work).
        size_t noff = (size_t)(b + 1) * step;
        float wA = xA[noff];
        float wB = xB[noff];

        // Phase 2: passthrough stores + Welford on current samples
        // (their data arrived during the previous iteration).
        size_t coff = (size_t)b * step;
        oA[coff] = vA;
        oB[coff] = vB;

        nnA += (vA != 0.0f);
        nnB += (vB != 0.0f);
        float invA = __fdividef(1.0f, nfA + 1.0f);
        float invB = __fdividef(1.0f, nfB + 1.0f);
        float om;
        om = mA; mA += (vA - mA) * invA; sA += (vA - mA) * (vA - om);
        om = mB; mB += (vB - mB) * invB; sB += (vB - mB) * (vB - om);
        nfA += 1.0f;
        nfB += 1.0f;

        vA = wA; vB = wB;
    }

    // Epilogue: last sample of each stream.
    {
        size_t coff = (size_t)(H - 1) * step;
        oA[coff] = vA;
        oB[coff] = vB;

        nnA += (vA != 0.0f);
        nnB += (vB != 0.0f);
        float invA = __fdividef(1.0f, nfA + 1.0f);
        float invB = __fdividef(1.0f, nfB + 1.0f);
        float om;
        om = mA; mA += (vA - mA) * invA; sA += (vA - mA) * (vA - om);
        om = mB; mB += (vB - mB) * invB; sB += (vB - mB) * (vB - om);
    }

    // Exact Chan merge: A carries n0+H samples, B carries H samples.
    float nAf = (float)(n0 + H);
    float nBf = (float)H;
    float nTf = nAf + nBf;
    float invT = __fdividef(1.0f, nTf);
    float d  = mB - mA;
    float m  = mA + d * (nBf * invT);
    float s  = sA + sB + d * d * (nAf * nBf * invT);
    int   nn = nnA + nnB;

    size_t base = (size_t)B * step;
    out[base + p]            = m;
    out[base + step + p]     = s;
    out[base + 2 * step + p] = (float)nn;
    if (p == 0) {
        out[base + 3 * step] = (float)(n0 + B);
    }
}

extern "C" void kernel_launch(void* const* d_in, const int* in_sizes, int n_in,
                              void* d_out, int out_size)
{
    const float* x  = (const float*)d_in[0];
    const float* m  = (const float*)d_in[1];
    const float* s  = (const float*)d_in[2];
    const int*   nn = (const int*)d_in[3];
    const int*   n  = (const int*)d_in[4];
    float* out = (float*)d_out;

    const int CHW = in_sizes[1];          // 262144
    const int B   = in_sizes[0] / CHW;    // 256

    const int threads = 256;
    const int blocks = (CHW + threads - 1) / threads;  // 1024
    welford_dual_pipe<<<blocks, threads>>>(x, m, s, nn, n, out, B, CHW);
}

// round 11
// speedup vs baseline: 1.1102x; 1.0425x over previous
#include <cuda_runtime.h>
#include <cuda_bf16.h>

// Welford running mean/variance over batch dim of x: (B, C, H, W), B=256, CHW=262144.
// R11 = R1 (fastest measured kernel: 81.8us, regs=32, full occupancy, 6.03 TB/s)
//       + __stcs streaming hint on the x passthrough stores ONLY.
// The 256 MB of passthrough writes are write-once; evict-first stores avoid
// L2 write-allocate evicting read sectors. Everything else identical to R1.
//
// Output layout (float32, concatenated):
//   [0, B*CHW)     : x passthrough
//   [+0, +CHW)     : m
//   [+CHW, +2CHW)  : s
//   [+2CHW, +3CHW) : neuron_nonzero (int -> float)
//   [last]         : n_samples + B

__global__ void welford_kernel_scs(const float* __restrict__ x,
                                   const float* __restrict__ m_in,
                                   const float* __restrict__ s_in,
                                   const int*   __restrict__ nn_in,
                                   const int*   __restrict__ n_in,
                                   float* __restrict__ out,
                                   int B, int CHW)
{
    int p = blockIdx.x * blockDim.x + threadIdx.x;
    if (p >= CHW) return;

    float m  = m_in[p];
    float s  = s_in[p];
    int   nn = nn_in[p];
    const int n0 = n_in[0];

    const float* xp = x + p;
    float*       op = out + p;

    #pragma unroll 8
    for (int b = 0; b < B; ++b) {
        float xv = xp[(size_t)b * CHW];
        __stcs(&op[(size_t)b * CHW], xv);         // streaming passthrough store

        nn += (xv != 0.0f) ? 1 : 0;
        float old_m = m;
        float inv = __fdividef(1.0f, (float)(n0 + b + 1));
        m = m + (xv - m) * inv;
        s = s + (xv - m) * (xv - old_m);
    }

    size_t base = (size_t)B * (size_t)CHW;
    out[base + p]                   = m;
    out[base + (size_t)CHW + p]     = s;
    out[base + 2 * (size_t)CHW + p] = (float)nn;
    if (p == 0) {
        out[base + 3 * (size_t)CHW] = (float)(n0 + B);
    }
}

extern "C" void kernel_launch(void* const* d_in, const int* in_sizes, int n_in,
                              void* d_out, int out_size)
{
    const float* x  = (const float*)d_in[0];
    const float* m  = (const float*)d_in[1];
    const float* s  = (const float*)d_in[2];
    const int*   nn = (const int*)d_in[3];
    const int*   n  = (const int*)d_in[4];
    float* out = (float*)d_out;

    const int CHW = in_sizes[1];          // 262144
    const int B   = in_sizes[0] / CHW;    // 256

    const int threads = 256;
    const int blocks = (CHW + threads - 1) / threads;  // 1024
    welford_kernel_scs<<<blocks, threads>>>(x, m, s, nn, n, out, B, CHW);
}